// round 11
// baseline (speedup 1.0000x reference)
#include <cuda_runtime.h>
#include <cuda_bf16.h>
#include <cstdint>
#include <cstddef>

#define S_LEN 2048
#define HID   2048
#define NH    16
#define HD    128
#define BATCH 2
#define MROWS (BATCH * S_LEN)

// ---------------------------------------------------------------------------
// Scratch (allocation-free rule: device globals)
// ---------------------------------------------------------------------------
__device__ float g_q [(size_t)MROWS * HID];
__device__ float g_k [(size_t)MROWS * HID];
__device__ float g_ao[(size_t)MROWS * HID];

__device__ __nv_bfloat16 g_vhi[(size_t)MROWS * HID];
__device__ __nv_bfloat16 g_vlo[(size_t)MROWS * HID];

// ---------------------------------------------------------------------------
// helpers
// ---------------------------------------------------------------------------
__device__ __forceinline__ uint32_t smem_u32(const void* p) {
  uint32_t a;
  asm("{ .reg .u64 t; cvta.to.shared.u64 t, %1; cvt.u32.u64 %0, t; }"
      : "=r"(a) : "l"(p));
  return a;
}

__device__ __forceinline__ void ldsm4(uint32_t addr, uint32_t& r0, uint32_t& r1,
                                      uint32_t& r2, uint32_t& r3) {
  asm volatile("ldmatrix.sync.aligned.m8n8.x4.shared.b16 {%0,%1,%2,%3}, [%4];"
               : "=r"(r0), "=r"(r1), "=r"(r2), "=r"(r3) : "r"(addr));
}

__device__ __forceinline__ void ldsm4t(uint32_t addr, uint32_t& r0, uint32_t& r1,
                                       uint32_t& r2, uint32_t& r3) {
  asm volatile("ldmatrix.sync.aligned.m8n8.x4.trans.shared.b16 {%0,%1,%2,%3}, [%4];"
               : "=r"(r0), "=r"(r1), "=r"(r2), "=r"(r3) : "r"(addr));
}

__device__ __forceinline__ void mma16816(float* d, const uint32_t* a,
                                         const uint32_t* b) {
  asm volatile(
      "mma.sync.aligned.m16n8k16.row.col.f32.bf16.bf16.f32 "
      "{%0,%1,%2,%3}, {%4,%5,%6,%7}, {%8,%9}, {%0,%1,%2,%3};"
      : "+f"(d[0]), "+f"(d[1]), "+f"(d[2]), "+f"(d[3])
      : "r"(a[0]), "r"(a[1]), "r"(a[2]), "r"(a[3]), "r"(b[0]), "r"(b[1]));
}

__device__ __forceinline__ void mma1688_tf32(float* d, const uint32_t* a,
                                             const uint32_t* b) {
  asm volatile(
      "mma.sync.aligned.m16n8k8.row.col.f32.tf32.tf32.f32 "
      "{%0,%1,%2,%3}, {%4,%5,%6,%7}, {%8,%9}, {%0,%1,%2,%3};"
      : "+f"(d[0]), "+f"(d[1]), "+f"(d[2]), "+f"(d[3])
      : "r"(a[0]), "r"(a[1]), "r"(a[2]), "r"(a[3]), "r"(b[0]), "r"(b[1]));
}

__device__ __forceinline__ uint32_t f2tf32(float x) {
  uint32_t r;
  asm("cvt.rna.tf32.f32 %0, %1;" : "=r"(r) : "f"(x));
  return r;
}

#define CP_ASYNC16(saddr, gaddr) \
  asm volatile("cp.async.cg.shared.global [%0], [%1], 16;" \
               :: "r"(saddr), "l"(gaddr))
#define CP_COMMIT() asm volatile("cp.async.commit_group;")
#define CP_WAIT1()  asm volatile("cp.async.wait_group 1;")
#define CP_WAIT0()  asm volatile("cp.async.wait_group 0;")

// FFMA-only exp2 (no MUFU): magic-round + degree-6 Taylor, |err| < 2e-7.
__device__ __forceinline__ float exp2p(float x) {
  x = fmaxf(x, -126.f);
  float r = x + 12582912.f;
  int   e = __float_as_int(r) - 0x4B400000;
  float f = x - (r - 12582912.f);
  float p = 1.5403e-4f;
  p = fmaf(p, f, 1.3333558e-3f);
  p = fmaf(p, f, 9.6181291e-3f);
  p = fmaf(p, f, 5.5504109e-2f);
  p = fmaf(p, f, 2.4022651e-1f);
  p = fmaf(p, f, 6.9314718e-1f);
  p = fmaf(p, f, 1.0f);
  return __int_as_float(__float_as_int(p) + (e << 23));
}

__device__ __forceinline__ uint32_t pack_bf16(float x, float y) {
  __nv_bfloat162 t = __floats2bfloat162_rn(x, y);
  return *(uint32_t*)&t;
}

// ---------------------------------------------------------------------------
// TF32 GEMM: C[m,n] = sum_k A[m,k]*W[n,k] (+bias).
// Optional epilogue: write bf16 hi/lo split instead of fp32 (V projection).
// ---------------------------------------------------------------------------
#define BKT 32
#define NCHT (HID / BKT)
#define TSTRT 36
#define TELEMT (128 * TSTRT)
#define GEMM_T_SMEM (2 * 2 * TELEMT * 4)

__global__ __launch_bounds__(256, 2) void gemm_tf32(
    const float* __restrict__ A, const float* __restrict__ W,
    const float* __restrict__ bias, float* __restrict__ C,
    __nv_bfloat16* __restrict__ hiO, __nv_bfloat16* __restrict__ loO) {
  extern __shared__ float smf[];
  const uint32_t sbase = smem_u32(smf);
  const int tid  = threadIdx.x;
  const int wid  = tid >> 5;
  const int lane = tid & 31;
  const int bm = blockIdx.y << 7;
  const int bn = blockIdx.x << 7;
  const int warp_m = (wid & 1) << 6;
  const int warp_n = (wid >> 1) << 5;

  const float* gp[2] = {A + (size_t)bm * HID, W + (size_t)bn * HID};

  auto issue_chunk = [&](int c) {
    const int p = c & 1;
    const int k0 = c * BKT;
    const uint32_t s0 = sbase + p * 2 * TELEMT * 4;
#pragma unroll
    for (int t = 0; t < 2; t++) {
#pragma unroll
      for (int i = 0; i < 4; i++) {
        int u = tid + (i << 8);
        int row = u >> 3;
        int g = (u & 7) << 2;
        const float* ga = gp[t] + (size_t)row * HID + k0 + g;
        uint32_t sa = s0 + (t * TELEMT + row * TSTRT + g) * 4;
        CP_ASYNC16(sa, ga);
      }
    }
    CP_COMMIT();
  };

  float acc[4][4][4];
#pragma unroll
  for (int mt = 0; mt < 4; mt++)
#pragma unroll
    for (int nt = 0; nt < 4; nt++)
#pragma unroll
      for (int r = 0; r < 4; r++) acc[mt][nt][r] = 0.f;

  issue_chunk(0);

  for (int c = 0; c < NCHT; c++) {
    if (c + 1 < NCHT) { issue_chunk(c + 1); CP_WAIT1(); }
    else              { CP_WAIT0(); }
    __syncthreads();

    const float* sA = smf + (c & 1) * 2 * TELEMT;
    const float* sB = sA + TELEMT;

#pragma unroll
    for (int ks = 0; ks < 4; ks++) {
      const int kc = ks << 3;
      uint32_t a[4][4];
      const int r0 = warp_m + (lane >> 2);
      const int ca = kc + (lane & 3);
#pragma unroll
      for (int mt = 0; mt < 4; mt++) {
        const int rr = r0 + (mt << 4);
        a[mt][0] = f2tf32(sA[rr * TSTRT + ca]);
        a[mt][1] = f2tf32(sA[(rr + 8) * TSTRT + ca]);
        a[mt][2] = f2tf32(sA[rr * TSTRT + ca + 4]);
        a[mt][3] = f2tf32(sA[(rr + 8) * TSTRT + ca + 4]);
      }
      uint32_t b[4][2];
      const int n0 = warp_n + (lane >> 2);
      const int cb = kc + (lane & 3);
#pragma unroll
      for (int nt = 0; nt < 4; nt++) {
        const int nn = n0 + (nt << 3);
        b[nt][0] = f2tf32(sB[nn * TSTRT + cb]);
        b[nt][1] = f2tf32(sB[nn * TSTRT + cb + 4]);
      }
#pragma unroll
      for (int mt = 0; mt < 4; mt++)
#pragma unroll
        for (int nt = 0; nt < 4; nt++)
          mma1688_tf32(acc[mt][nt], a[mt], b[nt]);
    }
    __syncthreads();
  }

  const int r  = lane >> 2;
  const int c2 = (lane & 3) << 1;
#pragma unroll
  for (int mt = 0; mt < 4; mt++) {
    const int row0 = bm + warp_m + (mt << 4) + r;
#pragma unroll
    for (int nt = 0; nt < 4; nt++) {
      const int col = bn + warp_n + (nt << 3) + c2;
      float b0 = 0.f, b1 = 0.f;
      if (bias) { b0 = bias[col]; b1 = bias[col + 1]; }
      float v00 = acc[mt][nt][0] + b0, v01 = acc[mt][nt][1] + b1;
      float v10 = acc[mt][nt][2] + b0, v11 = acc[mt][nt][3] + b1;
      if (hiO) {
        __nv_bfloat16 h00 = __float2bfloat16_rn(v00);
        __nv_bfloat16 h01 = __float2bfloat16_rn(v01);
        __nv_bfloat16 h10 = __float2bfloat16_rn(v10);
        __nv_bfloat16 h11 = __float2bfloat16_rn(v11);
        *(uint32_t*)&hiO[(size_t)row0 * HID + col] = pack_bf16(v00, v01);
        *(uint32_t*)&hiO[(size_t)(row0 + 8) * HID + col] = pack_bf16(v10, v11);
        *(uint32_t*)&loO[(size_t)row0 * HID + col] =
            pack_bf16(v00 - __bfloat162float(h00), v01 - __bfloat162float(h01));
        *(uint32_t*)&loO[(size_t)(row0 + 8) * HID + col] =
            pack_bf16(v10 - __bfloat162float(h10), v11 - __bfloat162float(h11));
      } else {
        float2 o0 = {v00, v01};
        float2 o1 = {v10, v11};
        *(float2*)&C[(size_t)row0 * HID + col]       = o0;
        *(float2*)&C[(size_t)(row0 + 8) * HID + col] = o1;
      }
    }
  }
}

// ---------------------------------------------------------------------------
// RoPE in place, tf32-rounded (rna) fp32 outputs. q gets scale*log2(e).
// ---------------------------------------------------------------------------
__global__ void rope_tf32(float* __restrict__ q, float* __restrict__ k,
                          const float* __restrict__ cosb,
                          const float* __restrict__ sinb)
{
  const float SC = 0.08838834764831845f * 1.4426950408889634f;
  int i = blockIdx.x * blockDim.x + threadIdx.x;
  int d  = i & 63;
  int h  = (i >> 6) & 15;
  int ms = i >> 10;
  int s  = ms & (S_LEN - 1);
  size_t base = (size_t)ms * HID + (size_t)h * HD;

  float c1 = cosb[s * HD + d],      s1 = sinb[s * HD + d];
  float c2 = cosb[s * HD + d + 64], s2 = sinb[s * HD + d + 64];

  float q1 = q[base + d], q2 = q[base + d + 64];
  float qa = (q1 * c1 - q2 * s1) * SC;
  float qb = (q2 * c2 + q1 * s2) * SC;
  float k1 = k[base + d], k2 = k[base + d + 64];
  float ka = k1 * c1 - k2 * s1;
  float kb = k2 * c2 + k1 * s2;

  q[base + d]      = __uint_as_float(f2tf32(qa));
  q[base + d + 64] = __uint_as_float(f2tf32(qb));
  k[base + d]      = __uint_as_float(f2tf32(ka));
  k[base + d + 64] = __uint_as_float(f2tf32(kb));
}

// ---------------------------------------------------------------------------
// Flash attention: tf32 QK^T + bf16x3 PV, exp2 softmax, deferred PV(t-1).
// CTA: 64 q-rows, 4 warps, 2 CTAs/SM. Q tf32 fragments via direct LDG
// (no Q smem). K fp32 double-buffered; V bf16 hi/lo TRIPLE-buffered so
// PV(t-1) can run between QK(t) and softmax(t), hiding softmax latency
// behind independent PV MMAs.
// ---------------------------------------------------------------------------
#define QSTRF 132                      // floats per K smem row (33x16B, odd)
#define VSTRB 136                      // bf16 per V smem row (17x16B, odd)
#define Q_ROWS 64
#define KV_ROWS 32
#define KF_BYTES (KV_ROWS * QSTRF * 4)         // 16896
#define VH_BYTES (KV_ROWS * VSTRB * 2)         // 8704
#define VSTAGE_BYTES (2 * VH_BYTES)            // 17408 (hi+lo)
#define A_SMEM (2 * KF_BYTES + 3 * VSTAGE_BYTES)  // 86016

__global__ __launch_bounds__(128, 2) void attn_mma(
    const float* __restrict__ q, const float* __restrict__ k,
    const __nv_bfloat16* __restrict__ vhi, const __nv_bfloat16* __restrict__ vlo,
    float* __restrict__ O)
{
  extern __shared__ char sma[];
  const uint32_t sb = smem_u32(sma);
  const int tid  = threadIdx.x;
  const int wid  = tid >> 5;
  const int lane = tid & 31;
  const int q0 = blockIdx.x << 6;          // 64 q-rows per CTA
  const int b  = blockIdx.y >> 4;
  const int h  = blockIdx.y & 15;
  const int warp_m = wid << 4;             // 0,16,32,48

  const size_t bS = (size_t)b * S_LEN;
  const size_t h128 = (size_t)h * HD;

  const uint32_t sK0 = sb;
  const uint32_t sV0 = sb + 2 * KF_BYTES;

  auto issue_kv = [&](int t) {
    const uint32_t kb = sK0 + (uint32_t)(t & 1) * KF_BYTES;
    const uint32_t vb = sV0 + (uint32_t)(t % 3) * VSTAGE_BYTES;
    const int kv0 = t << 5;
    // K fp32: 32 rows x 32 16B-chunks
#pragma unroll
    for (int i = 0; i < 8; i++) {
      int u = tid + (i << 7);
      int row = u >> 5, ch = u & 31;
      size_t g = (bS + kv0 + row) * HID + h128 + ch * 4;
      CP_ASYNC16(kb + (uint32_t)(row * QSTRF + ch * 4) * 4, k + g);
    }
    // V hi/lo bf16: 32 rows x 16 chunks each
#pragma unroll
    for (int i = 0; i < 4; i++) {
      int u = tid + (i << 7);
      int row = u >> 4, c8 = (u & 15) << 3;
      size_t g = (bS + kv0 + row) * HID + h128 + c8;
      uint32_t so = (uint32_t)(row * VSTRB + c8) * 2;
      CP_ASYNC16(vb + so,            vhi + g);
      CP_ASYNC16(vb + VH_BYTES + so, vlo + g);
    }
    CP_COMMIT();
  };
  issue_kv(0);
  issue_kv(1);

  // ---- Q tf32 fragments via direct LDG (values pre-rounded rna tf32)
  uint32_t aQ[16][4];
  {
    const int r0 = warp_m + (lane >> 2);
    const int c0 = lane & 3;
    const float* gq = q + (bS + q0 + r0) * HID + h128 + c0;
#pragma unroll
    for (int ks = 0; ks < 16; ks++) {
      const float* p = gq + (ks << 3);
      aQ[ks][0] = __float_as_uint(p[0]);
      aQ[ks][1] = __float_as_uint(p[8 * HID]);
      aQ[ks][2] = __float_as_uint(p[4]);
      aQ[ks][3] = __float_as_uint(p[8 * HID + 4]);
    }
  }

  float m0 = -1e30f, m1 = -1e30f, l0 = 0.f, l1 = 0.f;
  float Oa[16][4];
#pragma unroll
  for (int j = 0; j < 16; j++)
#pragma unroll
    for (int r = 0; r < 4; r++) Oa[j][r] = 0.f;

  uint32_t ph[4][2], pl[4][2];   // P fragments (previous tile)

  auto do_pv = [&](int pt) {
    const uint32_t vb = sV0 + (uint32_t)(pt % 3) * VSTAGE_BYTES;
    const uint32_t sVhi = vb;
    const uint32_t sVlo = vb + VH_BYTES;
#pragma unroll
    for (int kk = 0; kk < 2; kk++) {
      uint32_t paH[4] = {ph[kk*2][0], ph[kk*2][1], ph[kk*2+1][0], ph[kk*2+1][1]};
      uint32_t paL[4] = {pl[kk*2][0], pl[kk*2][1], pl[kk*2+1][0], pl[kk*2+1][1]};
#pragma unroll
      for (int dp = 0; dp < 8; dp++) {
        uint32_t bH[4], bL[4];
        const uint32_t voff =
            (uint32_t)(((kk << 4) + (lane & 7) + (((lane >> 3) & 1) << 3)) * VSTRB
                       + (dp << 4) + ((lane >> 4) << 3)) * 2;
        ldsm4t(sVhi + voff, bH[0], bH[1], bH[2], bH[3]);
        ldsm4t(sVlo + voff, bL[0], bL[1], bL[2], bL[3]);
        mma16816(Oa[dp * 2],     paH, bH);
        mma16816(Oa[dp * 2],     paH, bL);
        mma16816(Oa[dp * 2],     paL, bH);
        mma16816(Oa[dp * 2 + 1], paH, bH + 2);
        mma16816(Oa[dp * 2 + 1], paH, bL + 2);
        mma16816(Oa[dp * 2 + 1], paL, bH + 2);
      }
    }
  };

  const int lrow = lane & 15;
  const int lcg  = (lane >> 4) << 2;   // 0 or 4 (fp32 cols)

  const int NT = S_LEN / KV_ROWS;   // 64
  for (int t = 0; t < NT; t++) {
    if (t < NT - 1) CP_WAIT1(); else CP_WAIT0();
    __syncthreads();   // stage t ready; all warps done with reused slots

    const uint32_t sK = sK0 + (uint32_t)(t & 1) * KF_BYTES;

    // ---- QK(t): tf32, 16 x 32 scores
    float S[4][4];
#pragma unroll
    for (int j = 0; j < 4; j++)
#pragma unroll
      for (int r = 0; r < 4; r++) S[j][r] = 0.f;

#pragma unroll
    for (int ks = 0; ks < 16; ks++) {
      uint32_t bkf[4][2];
#pragma unroll
      for (int p = 0; p < 2; p++) {
        uint32_t m0r, m1r, m2r, m3r;
        const uint32_t addr =
            sK + (uint32_t)(((p << 4) + lrow) * QSTRF + (ks << 3) + lcg) * 4;
        ldsm4(addr, m0r, m1r, m2r, m3r);
        bkf[p * 2][0]     = m0r; bkf[p * 2][1]     = m2r;
        bkf[p * 2 + 1][0] = m1r; bkf[p * 2 + 1][1] = m3r;
      }
#pragma unroll
      for (int nt = 0; nt < 4; nt++)
        mma1688_tf32(S[nt], aQ[ks], bkf[nt]);
    }

    // ---- PV(t-1): independent MMA stream hiding softmax(t) latency
    if (t > 0) do_pv(t - 1);

    // ---- softmax(t) (exp2 domain); Oa rescale AFTER PV(t-1)
    float mx0 = m0, mx1 = m1;
#pragma unroll
    for (int j = 0; j < 4; j++) {
      mx0 = fmaxf(mx0, fmaxf(S[j][0], S[j][1]));
      mx1 = fmaxf(mx1, fmaxf(S[j][2], S[j][3]));
    }
    mx0 = fmaxf(mx0, __shfl_xor_sync(0xffffffffu, mx0, 1));
    mx0 = fmaxf(mx0, __shfl_xor_sync(0xffffffffu, mx0, 2));
    mx1 = fmaxf(mx1, __shfl_xor_sync(0xffffffffu, mx1, 1));
    mx1 = fmaxf(mx1, __shfl_xor_sync(0xffffffffu, mx1, 2));
    const float al0 = exp2p(m0 - mx0);
    const float al1 = exp2p(m1 - mx1);
    m0 = mx0; m1 = mx1;

    float sum0 = 0.f, sum1 = 0.f;
#pragma unroll
    for (int j = 0; j < 4; j++) {
      float p00 = exp2p(S[j][0] - mx0);
      float p01 = exp2p(S[j][1] - mx0);
      float p10 = exp2p(S[j][2] - mx1);
      float p11 = exp2p(S[j][3] - mx1);
      sum0 += p00 + p01;
      sum1 += p10 + p11;
      float h00 = __bfloat162float(__float2bfloat16_rn(p00));
      float h01 = __bfloat162float(__float2bfloat16_rn(p01));
      float h10 = __bfloat162float(__float2bfloat16_rn(p10));
      float h11 = __bfloat162float(__float2bfloat16_rn(p11));
      ph[j][0] = pack_bf16(h00, h01);
      ph[j][1] = pack_bf16(h10, h11);
      pl[j][0] = pack_bf16(p00 - h00, p01 - h01);
      pl[j][1] = pack_bf16(p10 - h10, p11 - h11);
    }
    l0 = l0 * al0 + sum0;
    l1 = l1 * al1 + sum1;
#pragma unroll
    for (int j = 0; j < 16; j++) {
      Oa[j][0] *= al0; Oa[j][1] *= al0;
      Oa[j][2] *= al1; Oa[j][3] *= al1;
    }

    __syncthreads();   // all warps done with K(t) and V(t-1)
    if (t + 2 < NT) issue_kv(t + 2);
  }

  // ---- tail PV
  do_pv(NT - 1);

  // ---- epilogue
  l0 += __shfl_xor_sync(0xffffffffu, l0, 1);
  l0 += __shfl_xor_sync(0xffffffffu, l0, 2);
  l1 += __shfl_xor_sync(0xffffffffu, l1, 1);
  l1 += __shfl_xor_sync(0xffffffffu, l1, 2);
  const float inv0 = 1.f / l0;
  const float inv1 = 1.f / l1;
  const int row0 = q0 + warp_m + (lane >> 2);
  const int cofs = (lane & 3) << 1;
#pragma unroll
  for (int j = 0; j < 16; j++) {
    const int col = (j << 3) + cofs;
    float2 v0 = {Oa[j][0] * inv0, Oa[j][1] * inv0};
    float2 v1 = {Oa[j][2] * inv1, Oa[j][3] * inv1};
    *(float2*)&O[(bS + row0) * HID + h128 + col]     = v0;
    *(float2*)&O[(bS + row0 + 8) * HID + h128 + col] = v1;
  }
}

// ---------------------------------------------------------------------------
extern "C" void kernel_launch(void* const* d_in, const int* in_sizes, int n_in,
                              void* d_out, int out_size)
{
  (void)in_sizes; (void)n_in; (void)out_size;
  const float* x    = (const float*)d_in[0];
  const float* cosb = (const float*)d_in[1];
  const float* sinb = (const float*)d_in[2];
  const float* wq   = (const float*)d_in[3];
  const float* bq   = (const float*)d_in[4];
  const float* wk   = (const float*)d_in[5];
  const float* bk   = (const float*)d_in[6];
  const float* wv   = (const float*)d_in[7];
  const float* bv   = (const float*)d_in[8];
  const float* wo   = (const float*)d_in[9];
  float* out = (float*)d_out;

  float *q, *k, *ao;
  cudaGetSymbolAddress((void**)&q,  g_q);
  cudaGetSymbolAddress((void**)&k,  g_k);
  cudaGetSymbolAddress((void**)&ao, g_ao);

  __nv_bfloat16 *vhi, *vlo;
  cudaGetSymbolAddress((void**)&vhi, g_vhi);
  cudaGetSymbolAddress((void**)&vlo, g_vlo);

  static bool attrs_set = false;
  if (!attrs_set) {
    cudaFuncSetAttribute(gemm_tf32,
                         cudaFuncAttributeMaxDynamicSharedMemorySize, GEMM_T_SMEM);
    cudaFuncSetAttribute(attn_mma,
                         cudaFuncAttributeMaxDynamicSharedMemorySize, A_SMEM);
    attrs_set = true;
  }

  dim3 gg(HID / 128, MROWS / 128);  // (16, 32)
  gemm_tf32<<<gg, 256, GEMM_T_SMEM>>>(x, wq, bq, q,  nullptr, nullptr);
  gemm_tf32<<<gg, 256, GEMM_T_SMEM>>>(x, wk, bk, k,  nullptr, nullptr);
  gemm_tf32<<<gg, 256, GEMM_T_SMEM>>>(x, wv, bv, nullptr, vhi, vlo);  // fused V split

  rope_tf32<<<(MROWS * NH * 64) / 256, 256>>>(q, k, cosb, sinb);

  attn_mma<<<dim3(S_LEN / Q_ROWS, BATCH * NH), 128, A_SMEM>>>(q, k, vhi, vlo, ao);

  gemm_tf32<<<gg, 256, GEMM_T_SMEM>>>(ao, wo, nullptr, out, nullptr, nullptr);
}

// round 12
// speedup vs baseline: 1.1864x; 1.1864x over previous
#include <cuda_runtime.h>
#include <cuda_bf16.h>
#include <cuda_fp16.h>
#include <cstdint>
#include <cstddef>

#define S_LEN 2048
#define HID   2048
#define NH    16
#define HD    128
#define BATCH 2
#define MROWS (BATCH * S_LEN)

// ---------------------------------------------------------------------------
// Scratch (allocation-free rule: device globals)
// ---------------------------------------------------------------------------
__device__ float g_q [(size_t)MROWS * HID];
__device__ float g_k [(size_t)MROWS * HID];
__device__ float g_ao[(size_t)MROWS * HID];

__device__ __half g_qh[(size_t)MROWS * HID];
__device__ __half g_kh[(size_t)MROWS * HID];
__device__ __half g_vh[(size_t)MROWS * HID];

// ---------------------------------------------------------------------------
// helpers
// ---------------------------------------------------------------------------
__device__ __forceinline__ uint32_t smem_u32(const void* p) {
  uint32_t a;
  asm("{ .reg .u64 t; cvta.to.shared.u64 t, %1; cvt.u32.u64 %0, t; }"
      : "=r"(a) : "l"(p));
  return a;
}

__device__ __forceinline__ void ldsm4(uint32_t addr, uint32_t& r0, uint32_t& r1,
                                      uint32_t& r2, uint32_t& r3) {
  asm volatile("ldmatrix.sync.aligned.m8n8.x4.shared.b16 {%0,%1,%2,%3}, [%4];"
               : "=r"(r0), "=r"(r1), "=r"(r2), "=r"(r3) : "r"(addr));
}

__device__ __forceinline__ void ldsm4t(uint32_t addr, uint32_t& r0, uint32_t& r1,
                                       uint32_t& r2, uint32_t& r3) {
  asm volatile("ldmatrix.sync.aligned.m8n8.x4.trans.shared.b16 {%0,%1,%2,%3}, [%4];"
               : "=r"(r0), "=r"(r1), "=r"(r2), "=r"(r3) : "r"(addr));
}

__device__ __forceinline__ void mma16816h(float* d, const uint32_t* a,
                                          const uint32_t* b) {
  asm volatile(
      "mma.sync.aligned.m16n8k16.row.col.f32.f16.f16.f32 "
      "{%0,%1,%2,%3}, {%4,%5,%6,%7}, {%8,%9}, {%0,%1,%2,%3};"
      : "+f"(d[0]), "+f"(d[1]), "+f"(d[2]), "+f"(d[3])
      : "r"(a[0]), "r"(a[1]), "r"(a[2]), "r"(a[3]), "r"(b[0]), "r"(b[1]));
}

__device__ __forceinline__ void mma1688_tf32(float* d, const uint32_t* a,
                                             const uint32_t* b) {
  asm volatile(
      "mma.sync.aligned.m16n8k8.row.col.f32.tf32.tf32.f32 "
      "{%0,%1,%2,%3}, {%4,%5,%6,%7}, {%8,%9}, {%0,%1,%2,%3};"
      : "+f"(d[0]), "+f"(d[1]), "+f"(d[2]), "+f"(d[3])
      : "r"(a[0]), "r"(a[1]), "r"(a[2]), "r"(a[3]), "r"(b[0]), "r"(b[1]));
}

__device__ __forceinline__ uint32_t f2tf32(float x) {
  uint32_t r;
  asm("cvt.rna.tf32.f32 %0, %1;" : "=r"(r) : "f"(x));
  return r;
}

#define CP_ASYNC16(saddr, gaddr) \
  asm volatile("cp.async.cg.shared.global [%0], [%1], 16;" \
               :: "r"(saddr), "l"(gaddr))
#define CP_COMMIT() asm volatile("cp.async.commit_group;")
#define CP_WAIT1()  asm volatile("cp.async.wait_group 1;")
#define CP_WAIT0()  asm volatile("cp.async.wait_group 0;")

// FFMA-only exp2 (no MUFU): magic-round + degree-6 Taylor, |err| < 2e-7.
__device__ __forceinline__ float exp2p(float x) {
  x = fmaxf(x, -126.f);
  float r = x + 12582912.f;
  int   e = __float_as_int(r) - 0x4B400000;
  float f = x - (r - 12582912.f);
  float p = 1.5403e-4f;
  p = fmaf(p, f, 1.3333558e-3f);
  p = fmaf(p, f, 9.6181291e-3f);
  p = fmaf(p, f, 5.5504109e-2f);
  p = fmaf(p, f, 2.4022651e-1f);
  p = fmaf(p, f, 6.9314718e-1f);
  p = fmaf(p, f, 1.0f);
  return __int_as_float(__float_as_int(p) + (e << 23));
}

__device__ __forceinline__ uint32_t pack_h(float x, float y) {
  __half2 t = __floats2half2_rn(x, y);
  return *(uint32_t*)&t;
}

// ---------------------------------------------------------------------------
// TF32 GEMM: C[m,n] = sum_k A[m,k]*W[n,k] (+bias).
// Optional epilogue: write fp16 (V projection) instead of fp32.
// ---------------------------------------------------------------------------
#define BKT 32
#define NCHT (HID / BKT)
#define TSTRT 36
#define TELEMT (128 * TSTRT)
#define GEMM_T_SMEM (2 * 2 * TELEMT * 4)

__global__ __launch_bounds__(256, 2) void gemm_tf32(
    const float* __restrict__ A, const float* __restrict__ W,
    const float* __restrict__ bias, float* __restrict__ C,
    __half* __restrict__ hO) {
  extern __shared__ float smf[];
  const uint32_t sbase = smem_u32(smf);
  const int tid  = threadIdx.x;
  const int wid  = tid >> 5;
  const int lane = tid & 31;
  const int bm = blockIdx.y << 7;
  const int bn = blockIdx.x << 7;
  const int warp_m = (wid & 1) << 6;
  const int warp_n = (wid >> 1) << 5;

  const float* gp[2] = {A + (size_t)bm * HID, W + (size_t)bn * HID};

  auto issue_chunk = [&](int c) {
    const int p = c & 1;
    const int k0 = c * BKT;
    const uint32_t s0 = sbase + p * 2 * TELEMT * 4;
#pragma unroll
    for (int t = 0; t < 2; t++) {
#pragma unroll
      for (int i = 0; i < 4; i++) {
        int u = tid + (i << 8);
        int row = u >> 3;
        int g = (u & 7) << 2;
        const float* ga = gp[t] + (size_t)row * HID + k0 + g;
        uint32_t sa = s0 + (t * TELEMT + row * TSTRT + g) * 4;
        CP_ASYNC16(sa, ga);
      }
    }
    CP_COMMIT();
  };

  float acc[4][4][4];
#pragma unroll
  for (int mt = 0; mt < 4; mt++)
#pragma unroll
    for (int nt = 0; nt < 4; nt++)
#pragma unroll
      for (int r = 0; r < 4; r++) acc[mt][nt][r] = 0.f;

  issue_chunk(0);

  for (int c = 0; c < NCHT; c++) {
    if (c + 1 < NCHT) { issue_chunk(c + 1); CP_WAIT1(); }
    else              { CP_WAIT0(); }
    __syncthreads();

    const float* sA = smf + (c & 1) * 2 * TELEMT;
    const float* sB = sA + TELEMT;

#pragma unroll
    for (int ks = 0; ks < 4; ks++) {
      const int kc = ks << 3;
      uint32_t a[4][4];
      const int r0 = warp_m + (lane >> 2);
      const int ca = kc + (lane & 3);
#pragma unroll
      for (int mt = 0; mt < 4; mt++) {
        const int rr = r0 + (mt << 4);
        a[mt][0] = f2tf32(sA[rr * TSTRT + ca]);
        a[mt][1] = f2tf32(sA[(rr + 8) * TSTRT + ca]);
        a[mt][2] = f2tf32(sA[rr * TSTRT + ca + 4]);
        a[mt][3] = f2tf32(sA[(rr + 8) * TSTRT + ca + 4]);
      }
      uint32_t b[4][2];
      const int n0 = warp_n + (lane >> 2);
      const int cb = kc + (lane & 3);
#pragma unroll
      for (int nt = 0; nt < 4; nt++) {
        const int nn = n0 + (nt << 3);
        b[nt][0] = f2tf32(sB[nn * TSTRT + cb]);
        b[nt][1] = f2tf32(sB[nn * TSTRT + cb + 4]);
      }
#pragma unroll
      for (int mt = 0; mt < 4; mt++)
#pragma unroll
        for (int nt = 0; nt < 4; nt++)
          mma1688_tf32(acc[mt][nt], a[mt], b[nt]);
    }
    __syncthreads();
  }

  const int r  = lane >> 2;
  const int c2 = (lane & 3) << 1;
#pragma unroll
  for (int mt = 0; mt < 4; mt++) {
    const int row0 = bm + warp_m + (mt << 4) + r;
#pragma unroll
    for (int nt = 0; nt < 4; nt++) {
      const int col = bn + warp_n + (nt << 3) + c2;
      float b0 = 0.f, b1 = 0.f;
      if (bias) { b0 = bias[col]; b1 = bias[col + 1]; }
      float v00 = acc[mt][nt][0] + b0, v01 = acc[mt][nt][1] + b1;
      float v10 = acc[mt][nt][2] + b0, v11 = acc[mt][nt][3] + b1;
      if (hO) {
        *(uint32_t*)&hO[(size_t)row0 * HID + col]       = pack_h(v00, v01);
        *(uint32_t*)&hO[(size_t)(row0 + 8) * HID + col] = pack_h(v10, v11);
      } else {
        float2 o0 = {v00, v01};
        float2 o1 = {v10, v11};
        *(float2*)&C[(size_t)row0 * HID + col]       = o0;
        *(float2*)&C[(size_t)(row0 + 8) * HID + col] = o1;
      }
    }
  }
}

// ---------------------------------------------------------------------------
// RoPE -> fp16 q/k. q gets scale*log2(e) folded in (exp2-domain softmax).
// ---------------------------------------------------------------------------
__global__ void rope_h(const float* __restrict__ q, const float* __restrict__ k,
                       const float* __restrict__ cosb, const float* __restrict__ sinb,
                       __half* __restrict__ qh, __half* __restrict__ kh)
{
  const float SC = 0.08838834764831845f * 1.4426950408889634f;
  int i = blockIdx.x * blockDim.x + threadIdx.x;
  int d  = i & 63;
  int h  = (i >> 6) & 15;
  int ms = i >> 10;
  int s  = ms & (S_LEN - 1);
  size_t base = (size_t)ms * HID + (size_t)h * HD;

  float c1 = cosb[s * HD + d],      s1 = sinb[s * HD + d];
  float c2 = cosb[s * HD + d + 64], s2 = sinb[s * HD + d + 64];

  float q1 = q[base + d], q2 = q[base + d + 64];
  float qa = (q1 * c1 - q2 * s1) * SC;
  float qb = (q2 * c2 + q1 * s2) * SC;
  float k1 = k[base + d], k2 = k[base + d + 64];
  float ka = k1 * c1 - k2 * s1;
  float kb = k2 * c2 + k1 * s2;

  qh[base + d]      = __float2half_rn(qa);
  qh[base + d + 64] = __float2half_rn(qb);
  kh[base + d]      = __float2half_rn(ka);
  kh[base + d + 64] = __float2half_rn(kb);
}

// ---------------------------------------------------------------------------
// Flash attention, ALL-fp16 MMA (single-pass QK and PV), exp2 softmax.
// CTA: 64 q-rows, 4 warps, 2 CTAs/SM. Q fp16 fragments via direct LDG.
// K/V fp16 double-buffered 32-row tiles. smem traffic and PV MMA halved
// vs the bf16x3/tf32 mix (the measured bind was smem+MMA serialization).
// ---------------------------------------------------------------------------
#define KSTR 136                      // fp16 per K/V smem row (17x16B, odd)
#define Q_ROWS 64
#define KV_ROWS 32
#define KH_BYTES (KV_ROWS * KSTR * 2)          // 8704
#define STAGE_BYTES (2 * KH_BYTES)             // K + V = 17408
#define A_SMEM (2 * STAGE_BYTES)               // 34816

__global__ __launch_bounds__(128, 2) void attn_h(
    const __half* __restrict__ qh, const __half* __restrict__ kh,
    const __half* __restrict__ vh, float* __restrict__ O)
{
  extern __shared__ char sma[];
  const uint32_t sb = smem_u32(sma);
  const int tid  = threadIdx.x;
  const int wid  = tid >> 5;
  const int lane = tid & 31;
  const int q0 = blockIdx.x << 6;          // 64 q-rows per CTA
  const int b  = blockIdx.y >> 4;
  const int h  = blockIdx.y & 15;
  const int warp_m = wid << 4;             // 0,16,32,48

  const size_t bS = (size_t)b * S_LEN;
  const size_t h128 = (size_t)h * HD;

  auto issue_kv = [&](int t) {
    const uint32_t stb = sb + (uint32_t)(t & 1) * STAGE_BYTES;
    const int kv0 = t << 5;
#pragma unroll
    for (int i = 0; i < 4; i++) {
      int u = tid + (i << 7);
      int row = u >> 4, c8 = (u & 15) << 3;
      size_t g = (bS + kv0 + row) * HID + h128 + c8;
      uint32_t so = (uint32_t)(row * KSTR + c8) * 2;
      CP_ASYNC16(stb + so,            kh + g);
      CP_ASYNC16(stb + KH_BYTES + so, vh + g);
    }
    CP_COMMIT();
  };
  issue_kv(0);
  issue_kv(1);

  // ---- Q fp16 fragments via direct LDG (m16n8k16 A-frag layout)
  uint32_t aQ[8][4];
  {
    const int r0 = warp_m + (lane >> 2);
    const int c0 = (lane & 3) << 1;
    const __half* gq = qh + (bS + q0 + r0) * HID + h128 + c0;
#pragma unroll
    for (int ks = 0; ks < 8; ks++) {
      const __half* p = gq + (ks << 4);
      aQ[ks][0] = *(const uint32_t*)(p);
      aQ[ks][1] = *(const uint32_t*)(p + 8 * HID);
      aQ[ks][2] = *(const uint32_t*)(p + 8);
      aQ[ks][3] = *(const uint32_t*)(p + 8 * HID + 8);
    }
  }

  float m0 = -1e30f, m1 = -1e30f, l0 = 0.f, l1 = 0.f;
  float Oa[16][4];
#pragma unroll
  for (int j = 0; j < 16; j++)
#pragma unroll
    for (int r = 0; r < 4; r++) Oa[j][r] = 0.f;

  const int NT = S_LEN / KV_ROWS;   // 64
  for (int t = 0; t < NT; t++) {
    if (t < NT - 1) CP_WAIT1(); else CP_WAIT0();
    __syncthreads();

    const uint32_t stb = sb + (uint32_t)(t & 1) * STAGE_BYTES;
    const uint32_t sK = stb;
    const uint32_t sV = stb + KH_BYTES;

    // ---- QK(t): fp16, 16 x 32 scores
    float S[4][4];
#pragma unroll
    for (int j = 0; j < 4; j++)
#pragma unroll
      for (int r = 0; r < 4; r++) S[j][r] = 0.f;

#pragma unroll
    for (int kc = 0; kc < 8; kc++) {
#pragma unroll
      for (int np = 0; np < 2; np++) {
        uint32_t bK[4];
        const uint32_t koff =
            (uint32_t)(((np << 4) + (lane & 7) + (((lane >> 4) & 1) << 3)) * KSTR
                       + (kc << 4) + (((lane >> 3) & 1) << 3)) * 2;
        ldsm4(sK + koff, bK[0], bK[1], bK[2], bK[3]);
        mma16816h(S[np * 2],     aQ[kc], bK);
        mma16816h(S[np * 2 + 1], aQ[kc], bK + 2);
      }
    }

    // ---- softmax(t) (exp2 domain)
    float mx0 = m0, mx1 = m1;
#pragma unroll
    for (int j = 0; j < 4; j++) {
      mx0 = fmaxf(mx0, fmaxf(S[j][0], S[j][1]));
      mx1 = fmaxf(mx1, fmaxf(S[j][2], S[j][3]));
    }
    mx0 = fmaxf(mx0, __shfl_xor_sync(0xffffffffu, mx0, 1));
    mx0 = fmaxf(mx0, __shfl_xor_sync(0xffffffffu, mx0, 2));
    mx1 = fmaxf(mx1, __shfl_xor_sync(0xffffffffu, mx1, 1));
    mx1 = fmaxf(mx1, __shfl_xor_sync(0xffffffffu, mx1, 2));
    const float al0 = exp2p(m0 - mx0);
    const float al1 = exp2p(m1 - mx1);
    m0 = mx0; m1 = mx1;

    uint32_t ph[4][2];
    float sum0 = 0.f, sum1 = 0.f;
#pragma unroll
    for (int j = 0; j < 4; j++) {
      float p00 = exp2p(S[j][0] - mx0);
      float p01 = exp2p(S[j][1] - mx0);
      float p10 = exp2p(S[j][2] - mx1);
      float p11 = exp2p(S[j][3] - mx1);
      sum0 += p00 + p01;
      sum1 += p10 + p11;
      ph[j][0] = pack_h(p00, p01);
      ph[j][1] = pack_h(p10, p11);
    }
    l0 = l0 * al0 + sum0;
    l1 = l1 * al1 + sum1;
#pragma unroll
    for (int j = 0; j < 16; j++) {
      Oa[j][0] *= al0; Oa[j][1] *= al0;
      Oa[j][2] *= al1; Oa[j][3] *= al1;
    }

    // ---- PV(t): fp16 single pass
#pragma unroll
    for (int kk = 0; kk < 2; kk++) {
      uint32_t paH[4] = {ph[kk*2][0], ph[kk*2][1], ph[kk*2+1][0], ph[kk*2+1][1]};
#pragma unroll
      for (int dp = 0; dp < 8; dp++) {
        uint32_t bV[4];
        const uint32_t voff =
            (uint32_t)(((kk << 4) + (lane & 7) + (((lane >> 3) & 1) << 3)) * KSTR
                       + (dp << 4) + ((lane >> 4) << 3)) * 2;
        ldsm4t(sV + voff, bV[0], bV[1], bV[2], bV[3]);
        mma16816h(Oa[dp * 2],     paH, bV);
        mma16816h(Oa[dp * 2 + 1], paH, bV + 2);
      }
    }

    __syncthreads();
    if (t + 2 < NT) issue_kv(t + 2);
  }

  // ---- epilogue
  l0 += __shfl_xor_sync(0xffffffffu, l0, 1);
  l0 += __shfl_xor_sync(0xffffffffu, l0, 2);
  l1 += __shfl_xor_sync(0xffffffffu, l1, 1);
  l1 += __shfl_xor_sync(0xffffffffu, l1, 2);
  const float inv0 = 1.f / l0;
  const float inv1 = 1.f / l1;
  const int row0 = q0 + warp_m + (lane >> 2);
  const int cofs = (lane & 3) << 1;
#pragma unroll
  for (int j = 0; j < 16; j++) {
    const int col = (j << 3) + cofs;
    float2 v0 = {Oa[j][0] * inv0, Oa[j][1] * inv0};
    float2 v1 = {Oa[j][2] * inv1, Oa[j][3] * inv1};
    *(float2*)&O[(bS + row0) * HID + h128 + col]     = v0;
    *(float2*)&O[(bS + row0 + 8) * HID + h128 + col] = v1;
  }
}

// ---------------------------------------------------------------------------
extern "C" void kernel_launch(void* const* d_in, const int* in_sizes, int n_in,
                              void* d_out, int out_size)
{
  (void)in_sizes; (void)n_in; (void)out_size;
  const float* x    = (const float*)d_in[0];
  const float* cosb = (const float*)d_in[1];
  const float* sinb = (const float*)d_in[2];
  const float* wq   = (const float*)d_in[3];
  const float* bq   = (const float*)d_in[4];
  const float* wk   = (const float*)d_in[5];
  const float* bk   = (const float*)d_in[6];
  const float* wv   = (const float*)d_in[7];
  const float* bv   = (const float*)d_in[8];
  const float* wo   = (const float*)d_in[9];
  float* out = (float*)d_out;

  float *q, *k, *ao;
  cudaGetSymbolAddress((void**)&q,  g_q);
  cudaGetSymbolAddress((void**)&k,  g_k);
  cudaGetSymbolAddress((void**)&ao, g_ao);

  __half *qh, *kh, *vh;
  cudaGetSymbolAddress((void**)&qh, g_qh);
  cudaGetSymbolAddress((void**)&kh, g_kh);
  cudaGetSymbolAddress((void**)&vh, g_vh);

  static bool attrs_set = false;
  if (!attrs_set) {
    cudaFuncSetAttribute(gemm_tf32,
                         cudaFuncAttributeMaxDynamicSharedMemorySize, GEMM_T_SMEM);
    cudaFuncSetAttribute(attn_h,
                         cudaFuncAttributeMaxDynamicSharedMemorySize, A_SMEM);
    attrs_set = true;
  }

  dim3 gg(HID / 128, MROWS / 128);  // (16, 32)
  gemm_tf32<<<gg, 256, GEMM_T_SMEM>>>(x, wq, bq, q,  nullptr);
  gemm_tf32<<<gg, 256, GEMM_T_SMEM>>>(x, wk, bk, k,  nullptr);
  gemm_tf32<<<gg, 256, GEMM_T_SMEM>>>(x, wv, bv, nullptr, vh);  // fused fp16 V

  rope_h<<<(MROWS * NH * 64) / 256, 256>>>(q, k, cosb, sinb, qh, kh);

  attn_h<<<dim3(S_LEN / Q_ROWS, BATCH * NH), 128, A_SMEM>>>(qh, kh, vh, ao);

  gemm_tf32<<<gg, 256, GEMM_T_SMEM>>>(ao, wo, nullptr, out, nullptr);
}

// round 13
// speedup vs baseline: 1.8031x; 1.5198x over previous
#include <cuda_runtime.h>
#include <cuda_fp16.h>
#include <cstdint>
#include <cstddef>

#define S_LEN 2048
#define HID   2048
#define NH    16
#define HD    128
#define BATCH 2
#define MROWS (BATCH * S_LEN)

// ---------------------------------------------------------------------------
// Scratch (allocation-free rule: device globals)
// ---------------------------------------------------------------------------
__device__ float g_q [(size_t)MROWS * HID];
__device__ float g_k [(size_t)MROWS * HID];

__device__ __half g_xh [(size_t)MROWS * HID];
__device__ __half g_wh [4][(size_t)HID * HID];
__device__ __half g_qh [(size_t)MROWS * HID];
__device__ __half g_kh [(size_t)MROWS * HID];
__device__ __half g_vh [(size_t)MROWS * HID];
__device__ __half g_aoh[(size_t)MROWS * HID];

// ---------------------------------------------------------------------------
// helpers
// ---------------------------------------------------------------------------
__device__ __forceinline__ uint32_t smem_u32(const void* p) {
  uint32_t a;
  asm("{ .reg .u64 t; cvta.to.shared.u64 t, %1; cvt.u32.u64 %0, t; }"
      : "=r"(a) : "l"(p));
  return a;
}

__device__ __forceinline__ void ldsm4(uint32_t addr, uint32_t& r0, uint32_t& r1,
                                      uint32_t& r2, uint32_t& r3) {
  asm volatile("ldmatrix.sync.aligned.m8n8.x4.shared.b16 {%0,%1,%2,%3}, [%4];"
               : "=r"(r0), "=r"(r1), "=r"(r2), "=r"(r3) : "r"(addr));
}

__device__ __forceinline__ void ldsm4t(uint32_t addr, uint32_t& r0, uint32_t& r1,
                                       uint32_t& r2, uint32_t& r3) {
  asm volatile("ldmatrix.sync.aligned.m8n8.x4.trans.shared.b16 {%0,%1,%2,%3}, [%4];"
               : "=r"(r0), "=r"(r1), "=r"(r2), "=r"(r3) : "r"(addr));
}

__device__ __forceinline__ void mma16816h(float* d, const uint32_t* a,
                                          const uint32_t* b) {
  asm volatile(
      "mma.sync.aligned.m16n8k16.row.col.f32.f16.f16.f32 "
      "{%0,%1,%2,%3}, {%4,%5,%6,%7}, {%8,%9}, {%0,%1,%2,%3};"
      : "+f"(d[0]), "+f"(d[1]), "+f"(d[2]), "+f"(d[3])
      : "r"(a[0]), "r"(a[1]), "r"(a[2]), "r"(a[3]), "r"(b[0]), "r"(b[1]));
}

#define CP_ASYNC16(saddr, gaddr) \
  asm volatile("cp.async.cg.shared.global [%0], [%1], 16;" \
               :: "r"(saddr), "l"(gaddr))
#define CP_COMMIT() asm volatile("cp.async.commit_group;")
#define CP_WAIT1()  asm volatile("cp.async.wait_group 1;")
#define CP_WAIT0()  asm volatile("cp.async.wait_group 0;")

// FFMA-only exp2 (no MUFU): magic-round + degree-6 Taylor, |err| < 2e-7.
__device__ __forceinline__ float exp2p(float x) {
  x = fmaxf(x, -126.f);
  float r = x + 12582912.f;
  int   e = __float_as_int(r) - 0x4B400000;
  float f = x - (r - 12582912.f);
  float p = 1.5403e-4f;
  p = fmaf(p, f, 1.3333558e-3f);
  p = fmaf(p, f, 9.6181291e-3f);
  p = fmaf(p, f, 5.5504109e-2f);
  p = fmaf(p, f, 2.4022651e-1f);
  p = fmaf(p, f, 6.9314718e-1f);
  p = fmaf(p, f, 1.0f);
  return __int_as_float(__float_as_int(p) + (e << 23));
}

__device__ __forceinline__ uint32_t pack_h(float x, float y) {
  __half2 t = __floats2half2_rn(x, y);
  return *(uint32_t*)&t;
}

// ---------------------------------------------------------------------------
// fp32 -> fp16 convert pass
// ---------------------------------------------------------------------------
__global__ void cvt_h(const float* __restrict__ in, __half* __restrict__ out,
                      int n) {
  int i = (blockIdx.x * blockDim.x + threadIdx.x) * 8;
  if (i >= n) return;
  float4 a = *(const float4*)(in + i);
  float4 b = *(const float4*)(in + i + 4);
  uint4 o;
  o.x = pack_h(a.x, a.y);
  o.y = pack_h(a.z, a.w);
  o.z = pack_h(b.x, b.y);
  o.w = pack_h(b.z, b.w);
  *(uint4*)(out + i) = o;
}

// ---------------------------------------------------------------------------
// fp16 HMMA GEMM: C[m,n] = sum_k A[m,k]*W[n,k] (+bias).
// CTA 128x128, BK=32, 8 warps of 64x32, double-buffered cp.async, 2 CTAs/SM.
// Layout = round-3/4 verified bf16 structure (TSTR 40, conflict-free ldsm),
// single fp16 pass. Optional fp16 output (V projection).
// ---------------------------------------------------------------------------
#define BKH 32
#define NCHH (HID / BKH)          // 64
#define TSTRH 40                  // fp16 per smem row
#define TELEMH (128 * TSTRH)      // 5120 elems/tile
#define GEMM_H_SMEM (2 * 2 * TELEMH * 2)   // 40960 bytes

__global__ __launch_bounds__(256, 2) void gemm_h(
    const __half* __restrict__ A, const __half* __restrict__ W,
    const float* __restrict__ bias, float* __restrict__ C,
    __half* __restrict__ hO) {
  extern __shared__ __half smh[];
  const uint32_t sbase = smem_u32(smh);
  const int tid  = threadIdx.x;
  const int wid  = tid >> 5;
  const int lane = tid & 31;
  const int bm = blockIdx.y << 7;
  const int bn = blockIdx.x << 7;
  const int warp_m = (wid & 1) << 6;   // 0 or 64
  const int warp_n = (wid >> 1) << 5;  // 0,32,64,96

  const __half* gp[2] = {A + (size_t)bm * HID, W + (size_t)bn * HID};

  auto issue_chunk = [&](int c) {
    const int p = c & 1;
    const int k0 = c * BKH;
    const uint32_t s0 = sbase + p * 2 * TELEMH * 2;
#pragma unroll
    for (int t = 0; t < 2; t++) {
#pragma unroll
      for (int i = 0; i < 2; i++) {
        int u = tid + (i << 8);
        int row = u >> 2;
        int cc = (u & 3) << 3;
        const __half* ga = gp[t] + (size_t)row * HID + k0 + cc;
        uint32_t sa = s0 + (t * TELEMH + row * TSTRH + cc) * 2;
        CP_ASYNC16(sa, ga);
      }
    }
    CP_COMMIT();
  };

  float acc[4][4][4];
#pragma unroll
  for (int mt = 0; mt < 4; mt++)
#pragma unroll
    for (int nt = 0; nt < 4; nt++)
#pragma unroll
      for (int r = 0; r < 4; r++) acc[mt][nt][r] = 0.f;

  issue_chunk(0);

  for (int c = 0; c < NCHH; c++) {
    if (c + 1 < NCHH) { issue_chunk(c + 1); CP_WAIT1(); }
    else              { CP_WAIT0(); }
    __syncthreads();

    const uint32_t buf = sbase + (c & 1) * 2 * TELEMH * 2;
    const uint32_t sA = buf;
    const uint32_t sB = buf + TELEMH * 2;

#pragma unroll
    for (int ks = 0; ks < 2; ks++) {
      const int kc = ks << 4;
      uint32_t a[4][4];
      const int arow = warp_m + (lane & 15);
      const int acol = kc + ((lane >> 4) << 3);
#pragma unroll
      for (int mt = 0; mt < 4; mt++) {
        uint32_t off = ((arow + (mt << 4)) * TSTRH + acol) * 2;
        ldsm4(sA + off, a[mt][0], a[mt][1], a[mt][2], a[mt][3]);
      }
      uint32_t b[4][2];
      const int brow0 = (lane & 7) + ((lane >> 4) << 3);
      const int bcol  = kc + (((lane >> 3) & 1) << 3);
#pragma unroll
      for (int pr = 0; pr < 2; pr++) {
        const int nb = warp_n + (pr << 4);
        uint32_t off = ((nb + brow0) * TSTRH + bcol) * 2;
        ldsm4(sB + off, b[pr*2][0], b[pr*2][1], b[pr*2+1][0], b[pr*2+1][1]);
      }
#pragma unroll
      for (int mt = 0; mt < 4; mt++)
#pragma unroll
        for (int nt = 0; nt < 4; nt++)
          mma16816h(acc[mt][nt], a[mt], b[nt]);
    }
    __syncthreads();
  }

  const int r  = lane >> 2;
  const int c2 = (lane & 3) << 1;
#pragma unroll
  for (int mt = 0; mt < 4; mt++) {
    const int row0 = bm + warp_m + (mt << 4) + r;
#pragma unroll
    for (int nt = 0; nt < 4; nt++) {
      const int col = bn + warp_n + (nt << 3) + c2;
      float b0 = 0.f, b1 = 0.f;
      if (bias) { b0 = bias[col]; b1 = bias[col + 1]; }
      float v00 = acc[mt][nt][0] + b0, v01 = acc[mt][nt][1] + b1;
      float v10 = acc[mt][nt][2] + b0, v11 = acc[mt][nt][3] + b1;
      if (hO) {
        *(uint32_t*)&hO[(size_t)row0 * HID + col]       = pack_h(v00, v01);
        *(uint32_t*)&hO[(size_t)(row0 + 8) * HID + col] = pack_h(v10, v11);
      } else {
        float2 o0 = {v00, v01};
        float2 o1 = {v10, v11};
        *(float2*)&C[(size_t)row0 * HID + col]       = o0;
        *(float2*)&C[(size_t)(row0 + 8) * HID + col] = o1;
      }
    }
  }
}

// ---------------------------------------------------------------------------
// RoPE -> fp16 q/k. q gets scale*log2(e) folded in (exp2-domain softmax).
// ---------------------------------------------------------------------------
__global__ void rope_h(const float* __restrict__ q, const float* __restrict__ k,
                       const float* __restrict__ cosb, const float* __restrict__ sinb,
                       __half* __restrict__ qh, __half* __restrict__ kh)
{
  const float SC = 0.08838834764831845f * 1.4426950408889634f;
  int i = blockIdx.x * blockDim.x + threadIdx.x;
  int d  = i & 63;
  int h  = (i >> 6) & 15;
  int ms = i >> 10;
  int s  = ms & (S_LEN - 1);
  size_t base = (size_t)ms * HID + (size_t)h * HD;

  float c1 = cosb[s * HD + d],      s1 = sinb[s * HD + d];
  float c2 = cosb[s * HD + d + 64], s2 = sinb[s * HD + d + 64];

  float q1 = q[base + d], q2 = q[base + d + 64];
  float qa = (q1 * c1 - q2 * s1) * SC;
  float qb = (q2 * c2 + q1 * s2) * SC;
  float k1 = k[base + d], k2 = k[base + d + 64];
  float ka = k1 * c1 - k2 * s1;
  float kb = k2 * c2 + k1 * s2;

  qh[base + d]      = __float2half_rn(qa);
  qh[base + d + 64] = __float2half_rn(qb);
  kh[base + d]      = __float2half_rn(ka);
  kh[base + d + 64] = __float2half_rn(kb);
}

// ---------------------------------------------------------------------------
// Flash attention, ALL-fp16 MMA (round-12 proven), exp2 softmax.
// Output written as fp16 (consumed by the fp16 o-proj GEMM).
// ---------------------------------------------------------------------------
#define KSTR 136
#define Q_ROWS 64
#define KV_ROWS 32
#define KH_BYTES (KV_ROWS * KSTR * 2)
#define STAGE_BYTES (2 * KH_BYTES)
#define A_SMEM (2 * STAGE_BYTES)               // 34816

__global__ __launch_bounds__(128, 2) void attn_h(
    const __half* __restrict__ qh, const __half* __restrict__ kh,
    const __half* __restrict__ vh, __half* __restrict__ O)
{
  extern __shared__ char sma[];
  const uint32_t sb = smem_u32(sma);
  const int tid  = threadIdx.x;
  const int wid  = tid >> 5;
  const int lane = tid & 31;
  const int q0 = blockIdx.x << 6;
  const int b  = blockIdx.y >> 4;
  const int h  = blockIdx.y & 15;
  const int warp_m = wid << 4;

  const size_t bS = (size_t)b * S_LEN;
  const size_t h128 = (size_t)h * HD;

  auto issue_kv = [&](int t) {
    const uint32_t stb = sb + (uint32_t)(t & 1) * STAGE_BYTES;
    const int kv0 = t << 5;
#pragma unroll
    for (int i = 0; i < 4; i++) {
      int u = tid + (i << 7);
      int row = u >> 4, c8 = (u & 15) << 3;
      size_t g = (bS + kv0 + row) * HID + h128 + c8;
      uint32_t so = (uint32_t)(row * KSTR + c8) * 2;
      CP_ASYNC16(stb + so,            kh + g);
      CP_ASYNC16(stb + KH_BYTES + so, vh + g);
    }
    CP_COMMIT();
  };
  issue_kv(0);
  issue_kv(1);

  uint32_t aQ[8][4];
  {
    const int r0 = warp_m + (lane >> 2);
    const int c0 = (lane & 3) << 1;
    const __half* gq = qh + (bS + q0 + r0) * HID + h128 + c0;
#pragma unroll
    for (int ks = 0; ks < 8; ks++) {
      const __half* p = gq + (ks << 4);
      aQ[ks][0] = *(const uint32_t*)(p);
      aQ[ks][1] = *(const uint32_t*)(p + 8 * HID);
      aQ[ks][2] = *(const uint32_t*)(p + 8);
      aQ[ks][3] = *(const uint32_t*)(p + 8 * HID + 8);
    }
  }

  float m0 = -1e30f, m1 = -1e30f, l0 = 0.f, l1 = 0.f;
  float Oa[16][4];
#pragma unroll
  for (int j = 0; j < 16; j++)
#pragma unroll
    for (int r = 0; r < 4; r++) Oa[j][r] = 0.f;

  const int NT = S_LEN / KV_ROWS;   // 64
  for (int t = 0; t < NT; t++) {
    if (t < NT - 1) CP_WAIT1(); else CP_WAIT0();
    __syncthreads();

    const uint32_t stb = sb + (uint32_t)(t & 1) * STAGE_BYTES;
    const uint32_t sK = stb;
    const uint32_t sV = stb + KH_BYTES;

    float S[4][4];
#pragma unroll
    for (int j = 0; j < 4; j++)
#pragma unroll
      for (int r = 0; r < 4; r++) S[j][r] = 0.f;

#pragma unroll
    for (int kc = 0; kc < 8; kc++) {
#pragma unroll
      for (int np = 0; np < 2; np++) {
        uint32_t bK[4];
        const uint32_t koff =
            (uint32_t)(((np << 4) + (lane & 7) + (((lane >> 4) & 1) << 3)) * KSTR
                       + (kc << 4) + (((lane >> 3) & 1) << 3)) * 2;
        ldsm4(sK + koff, bK[0], bK[1], bK[2], bK[3]);
        mma16816h(S[np * 2],     aQ[kc], bK);
        mma16816h(S[np * 2 + 1], aQ[kc], bK + 2);
      }
    }

    float mx0 = m0, mx1 = m1;
#pragma unroll
    for (int j = 0; j < 4; j++) {
      mx0 = fmaxf(mx0, fmaxf(S[j][0], S[j][1]));
      mx1 = fmaxf(mx1, fmaxf(S[j][2], S[j][3]));
    }
    mx0 = fmaxf(mx0, __shfl_xor_sync(0xffffffffu, mx0, 1));
    mx0 = fmaxf(mx0, __shfl_xor_sync(0xffffffffu, mx0, 2));
    mx1 = fmaxf(mx1, __shfl_xor_sync(0xffffffffu, mx1, 1));
    mx1 = fmaxf(mx1, __shfl_xor_sync(0xffffffffu, mx1, 2));
    const float al0 = exp2p(m0 - mx0);
    const float al1 = exp2p(m1 - mx1);
    m0 = mx0; m1 = mx1;

    uint32_t ph[4][2];
    float sum0 = 0.f, sum1 = 0.f;
#pragma unroll
    for (int j = 0; j < 4; j++) {
      float p00 = exp2p(S[j][0] - mx0);
      float p01 = exp2p(S[j][1] - mx0);
      float p10 = exp2p(S[j][2] - mx1);
      float p11 = exp2p(S[j][3] - mx1);
      sum0 += p00 + p01;
      sum1 += p10 + p11;
      ph[j][0] = pack_h(p00, p01);
      ph[j][1] = pack_h(p10, p11);
    }
    l0 = l0 * al0 + sum0;
    l1 = l1 * al1 + sum1;
#pragma unroll
    for (int j = 0; j < 16; j++) {
      Oa[j][0] *= al0; Oa[j][1] *= al0;
      Oa[j][2] *= al1; Oa[j][3] *= al1;
    }

#pragma unroll
    for (int kk = 0; kk < 2; kk++) {
      uint32_t paH[4] = {ph[kk*2][0], ph[kk*2][1], ph[kk*2+1][0], ph[kk*2+1][1]};
#pragma unroll
      for (int dp = 0; dp < 8; dp++) {
        uint32_t bV[4];
        const uint32_t voff =
            (uint32_t)(((kk << 4) + (lane & 7) + (((lane >> 3) & 1) << 3)) * KSTR
                       + (dp << 4) + ((lane >> 4) << 3)) * 2;
        ldsm4t(sV + voff, bV[0], bV[1], bV[2], bV[3]);
        mma16816h(Oa[dp * 2],     paH, bV);
        mma16816h(Oa[dp * 2 + 1], paH, bV + 2);
      }
    }

    __syncthreads();
    if (t + 2 < NT) issue_kv(t + 2);
  }

  // ---- epilogue (fp16 out)
  l0 += __shfl_xor_sync(0xffffffffu, l0, 1);
  l0 += __shfl_xor_sync(0xffffffffu, l0, 2);
  l1 += __shfl_xor_sync(0xffffffffu, l1, 1);
  l1 += __shfl_xor_sync(0xffffffffu, l1, 2);
  const float inv0 = 1.f / l0;
  const float inv1 = 1.f / l1;
  const int row0 = q0 + warp_m + (lane >> 2);
  const int cofs = (lane & 3) << 1;
#pragma unroll
  for (int j = 0; j < 16; j++) {
    const int col = (j << 3) + cofs;
    *(uint32_t*)&O[(bS + row0) * HID + h128 + col] =
        pack_h(Oa[j][0] * inv0, Oa[j][1] * inv0);
    *(uint32_t*)&O[(bS + row0 + 8) * HID + h128 + col] =
        pack_h(Oa[j][2] * inv1, Oa[j][3] * inv1);
  }
}

// ---------------------------------------------------------------------------
extern "C" void kernel_launch(void* const* d_in, const int* in_sizes, int n_in,
                              void* d_out, int out_size)
{
  (void)in_sizes; (void)n_in; (void)out_size;
  const float* x    = (const float*)d_in[0];
  const float* cosb = (const float*)d_in[1];
  const float* sinb = (const float*)d_in[2];
  const float* wq   = (const float*)d_in[3];
  const float* bq   = (const float*)d_in[4];
  const float* wk   = (const float*)d_in[5];
  const float* bk   = (const float*)d_in[6];
  const float* wv   = (const float*)d_in[7];
  const float* bv   = (const float*)d_in[8];
  const float* wo   = (const float*)d_in[9];
  float* out = (float*)d_out;

  float *q, *k;
  cudaGetSymbolAddress((void**)&q,  g_q);
  cudaGetSymbolAddress((void**)&k,  g_k);

  __half *xh, *wh, *qh, *kh, *vh, *aoh;
  cudaGetSymbolAddress((void**)&xh,  g_xh);
  cudaGetSymbolAddress((void**)&wh,  g_wh);
  cudaGetSymbolAddress((void**)&qh,  g_qh);
  cudaGetSymbolAddress((void**)&kh,  g_kh);
  cudaGetSymbolAddress((void**)&vh,  g_vh);
  cudaGetSymbolAddress((void**)&aoh, g_aoh);

  static bool attrs_set = false;
  if (!attrs_set) {
    cudaFuncSetAttribute(gemm_h,
                         cudaFuncAttributeMaxDynamicSharedMemorySize, GEMM_H_SMEM);
    cudaFuncSetAttribute(attn_h,
                         cudaFuncAttributeMaxDynamicSharedMemorySize, A_SMEM);
    attrs_set = true;
  }

  const int NX = MROWS * HID;   // 8388608
  const int NW = HID * HID;     // 4194304
  const size_t WS = (size_t)HID * HID;

  // one-time fp16 converts
  cvt_h<<<NX / 2048, 256>>>(x,  xh, NX);
  cvt_h<<<NW / 2048, 256>>>(wq, wh + 0 * WS, NW);
  cvt_h<<<NW / 2048, 256>>>(wk, wh + 1 * WS, NW);
  cvt_h<<<NW / 2048, 256>>>(wv, wh + 2 * WS, NW);
  cvt_h<<<NW / 2048, 256>>>(wo, wh + 3 * WS, NW);

  dim3 gg(HID / 128, MROWS / 128);  // (16, 32)
  gemm_h<<<gg, 256, GEMM_H_SMEM>>>(xh, wh + 0 * WS, bq, q, nullptr);
  gemm_h<<<gg, 256, GEMM_H_SMEM>>>(xh, wh + 1 * WS, bk, k, nullptr);
  gemm_h<<<gg, 256, GEMM_H_SMEM>>>(xh, wh + 2 * WS, bv, nullptr, vh);

  rope_h<<<(MROWS * NH * 64) / 256, 256>>>(q, k, cosb, sinb, qh, kh);

  attn_h<<<dim3(S_LEN / Q_ROWS, BATCH * NH), 128, A_SMEM>>>(qh, kh, vh, aoh);

  gemm_h<<<gg, 256, GEMM_H_SMEM>>>(aoh, wh + 3 * WS, nullptr, out, nullptr);
}

// round 14
// speedup vs baseline: 1.9139x; 1.0615x over previous
#include <cuda_runtime.h>
#include <cuda_fp16.h>
#include <cstdint>
#include <cstddef>

#define S_LEN 2048
#define HID   2048
#define NH    16
#define HD    128
#define BATCH 2
#define MROWS (BATCH * S_LEN)

// ---------------------------------------------------------------------------
// Scratch (allocation-free rule: device globals)
// ---------------------------------------------------------------------------
__device__ float g_q [(size_t)MROWS * HID];
__device__ float g_k [(size_t)MROWS * HID];

__device__ __half g_xh [(size_t)MROWS * HID];
__device__ __half g_wh [4][(size_t)HID * HID];
__device__ __half g_qh [(size_t)MROWS * HID];
__device__ __half g_kh [(size_t)MROWS * HID];
__device__ __half g_vh [(size_t)MROWS * HID];
__device__ __half g_aoh[(size_t)MROWS * HID];

// ---------------------------------------------------------------------------
// helpers
// ---------------------------------------------------------------------------
__device__ __forceinline__ uint32_t smem_u32(const void* p) {
  uint32_t a;
  asm("{ .reg .u64 t; cvta.to.shared.u64 t, %1; cvt.u32.u64 %0, t; }"
      : "=r"(a) : "l"(p));
  return a;
}

__device__ __forceinline__ void ldsm4(uint32_t addr, uint32_t& r0, uint32_t& r1,
                                      uint32_t& r2, uint32_t& r3) {
  asm volatile("ldmatrix.sync.aligned.m8n8.x4.shared.b16 {%0,%1,%2,%3}, [%4];"
               : "=r"(r0), "=r"(r1), "=r"(r2), "=r"(r3) : "r"(addr));
}

__device__ __forceinline__ void ldsm4t(uint32_t addr, uint32_t& r0, uint32_t& r1,
                                       uint32_t& r2, uint32_t& r3) {
  asm volatile("ldmatrix.sync.aligned.m8n8.x4.trans.shared.b16 {%0,%1,%2,%3}, [%4];"
               : "=r"(r0), "=r"(r1), "=r"(r2), "=r"(r3) : "r"(addr));
}

__device__ __forceinline__ void mma16816h(float* d, const uint32_t* a,
                                          const uint32_t* b) {
  asm volatile(
      "mma.sync.aligned.m16n8k16.row.col.f32.f16.f16.f32 "
      "{%0,%1,%2,%3}, {%4,%5,%6,%7}, {%8,%9}, {%0,%1,%2,%3};"
      : "+f"(d[0]), "+f"(d[1]), "+f"(d[2]), "+f"(d[3])
      : "r"(a[0]), "r"(a[1]), "r"(a[2]), "r"(a[3]), "r"(b[0]), "r"(b[1]));
}

#define CP_ASYNC16(saddr, gaddr) \
  asm volatile("cp.async.cg.shared.global [%0], [%1], 16;" \
               :: "r"(saddr), "l"(gaddr))
#define CP_COMMIT() asm volatile("cp.async.commit_group;")
#define CP_WAIT1()  asm volatile("cp.async.wait_group 1;")
#define CP_WAIT0()  asm volatile("cp.async.wait_group 0;")

// FFMA-only exp2 (no MUFU): magic-round + degree-6 Taylor, |err| < 2e-7.
__device__ __forceinline__ float exp2p(float x) {
  x = fmaxf(x, -126.f);
  float r = x + 12582912.f;
  int   e = __float_as_int(r) - 0x4B400000;
  float f = x - (r - 12582912.f);
  float p = 1.5403e-4f;
  p = fmaf(p, f, 1.3333558e-3f);
  p = fmaf(p, f, 9.6181291e-3f);
  p = fmaf(p, f, 5.5504109e-2f);
  p = fmaf(p, f, 2.4022651e-1f);
  p = fmaf(p, f, 6.9314718e-1f);
  p = fmaf(p, f, 1.0f);
  return __int_as_float(__float_as_int(p) + (e << 23));
}

__device__ __forceinline__ uint32_t pack_h(float x, float y) {
  __half2 t = __floats2half2_rn(x, y);
  return *(uint32_t*)&t;
}

// ---------------------------------------------------------------------------
// fp32 -> fp16 convert pass
// ---------------------------------------------------------------------------
__global__ void cvt_h(const float* __restrict__ in, __half* __restrict__ out,
                      int n) {
  int i = (blockIdx.x * blockDim.x + threadIdx.x) * 8;
  if (i >= n) return;
  float4 a = *(const float4*)(in + i);
  float4 b = *(const float4*)(in + i + 4);
  uint4 o;
  o.x = pack_h(a.x, a.y);
  o.y = pack_h(a.z, a.w);
  o.z = pack_h(b.x, b.y);
  o.w = pack_h(b.z, b.w);
  *(uint4*)(out + i) = o;
}

// ---------------------------------------------------------------------------
// fp16 HMMA GEMM (round-13 proven): C[m,n] = sum_k A[m,k]*W[n,k] (+bias)
// ---------------------------------------------------------------------------
#define BKH 32
#define NCHH (HID / BKH)
#define TSTRH 40
#define TELEMH (128 * TSTRH)
#define GEMM_H_SMEM (2 * 2 * TELEMH * 2)

__global__ __launch_bounds__(256, 2) void gemm_h(
    const __half* __restrict__ A, const __half* __restrict__ W,
    const float* __restrict__ bias, float* __restrict__ C,
    __half* __restrict__ hO) {
  extern __shared__ __half smh[];
  const uint32_t sbase = smem_u32(smh);
  const int tid  = threadIdx.x;
  const int wid  = tid >> 5;
  const int lane = tid & 31;
  const int bm = blockIdx.y << 7;
  const int bn = blockIdx.x << 7;
  const int warp_m = (wid & 1) << 6;
  const int warp_n = (wid >> 1) << 5;

  const __half* gp[2] = {A + (size_t)bm * HID, W + (size_t)bn * HID};

  auto issue_chunk = [&](int c) {
    const int p = c & 1;
    const int k0 = c * BKH;
    const uint32_t s0 = sbase + p * 2 * TELEMH * 2;
#pragma unroll
    for (int t = 0; t < 2; t++) {
#pragma unroll
      for (int i = 0; i < 2; i++) {
        int u = tid + (i << 8);
        int row = u >> 2;
        int cc = (u & 3) << 3;
        const __half* ga = gp[t] + (size_t)row * HID + k0 + cc;
        uint32_t sa = s0 + (t * TELEMH + row * TSTRH + cc) * 2;
        CP_ASYNC16(sa, ga);
      }
    }
    CP_COMMIT();
  };

  float acc[4][4][4];
#pragma unroll
  for (int mt = 0; mt < 4; mt++)
#pragma unroll
    for (int nt = 0; nt < 4; nt++)
#pragma unroll
      for (int r = 0; r < 4; r++) acc[mt][nt][r] = 0.f;

  issue_chunk(0);

  for (int c = 0; c < NCHH; c++) {
    if (c + 1 < NCHH) { issue_chunk(c + 1); CP_WAIT1(); }
    else              { CP_WAIT0(); }
    __syncthreads();

    const uint32_t buf = sbase + (c & 1) * 2 * TELEMH * 2;
    const uint32_t sA = buf;
    const uint32_t sB = buf + TELEMH * 2;

#pragma unroll
    for (int ks = 0; ks < 2; ks++) {
      const int kc = ks << 4;
      uint32_t a[4][4];
      const int arow = warp_m + (lane & 15);
      const int acol = kc + ((lane >> 4) << 3);
#pragma unroll
      for (int mt = 0; mt < 4; mt++) {
        uint32_t off = ((arow + (mt << 4)) * TSTRH + acol) * 2;
        ldsm4(sA + off, a[mt][0], a[mt][1], a[mt][2], a[mt][3]);
      }
      uint32_t b[4][2];
      const int brow0 = (lane & 7) + ((lane >> 4) << 3);
      const int bcol  = kc + (((lane >> 3) & 1) << 3);
#pragma unroll
      for (int pr = 0; pr < 2; pr++) {
        const int nb = warp_n + (pr << 4);
        uint32_t off = ((nb + brow0) * TSTRH + bcol) * 2;
        ldsm4(sB + off, b[pr*2][0], b[pr*2][1], b[pr*2+1][0], b[pr*2+1][1]);
      }
#pragma unroll
      for (int mt = 0; mt < 4; mt++)
#pragma unroll
        for (int nt = 0; nt < 4; nt++)
          mma16816h(acc[mt][nt], a[mt], b[nt]);
    }
    __syncthreads();
  }

  const int r  = lane >> 2;
  const int c2 = (lane & 3) << 1;
#pragma unroll
  for (int mt = 0; mt < 4; mt++) {
    const int row0 = bm + warp_m + (mt << 4) + r;
#pragma unroll
    for (int nt = 0; nt < 4; nt++) {
      const int col = bn + warp_n + (nt << 3) + c2;
      float b0 = 0.f, b1 = 0.f;
      if (bias) { b0 = bias[col]; b1 = bias[col + 1]; }
      float v00 = acc[mt][nt][0] + b0, v01 = acc[mt][nt][1] + b1;
      float v10 = acc[mt][nt][2] + b0, v11 = acc[mt][nt][3] + b1;
      if (hO) {
        *(uint32_t*)&hO[(size_t)row0 * HID + col]       = pack_h(v00, v01);
        *(uint32_t*)&hO[(size_t)(row0 + 8) * HID + col] = pack_h(v10, v11);
      } else {
        float2 o0 = {v00, v01};
        float2 o1 = {v10, v11};
        *(float2*)&C[(size_t)row0 * HID + col]       = o0;
        *(float2*)&C[(size_t)(row0 + 8) * HID + col] = o1;
      }
    }
  }
}

// ---------------------------------------------------------------------------
// RoPE -> fp16 q/k. q gets scale*log2(e) folded in (exp2-domain softmax).
// ---------------------------------------------------------------------------
__global__ void rope_h(const float* __restrict__ q, const float* __restrict__ k,
                       const float* __restrict__ cosb, const float* __restrict__ sinb,
                       __half* __restrict__ qh, __half* __restrict__ kh)
{
  const float SC = 0.08838834764831845f * 1.4426950408889634f;
  int i = blockIdx.x * blockDim.x + threadIdx.x;
  int d  = i & 63;
  int h  = (i >> 6) & 15;
  int ms = i >> 10;
  int s  = ms & (S_LEN - 1);
  size_t base = (size_t)ms * HID + (size_t)h * HD;

  float c1 = cosb[s * HD + d],      s1 = sinb[s * HD + d];
  float c2 = cosb[s * HD + d + 64], s2 = sinb[s * HD + d + 64];

  float q1 = q[base + d], q2 = q[base + d + 64];
  float qa = (q1 * c1 - q2 * s1) * SC;
  float qb = (q2 * c2 + q1 * s2) * SC;
  float k1 = k[base + d], k2 = k[base + d + 64];
  float ka = k1 * c1 - k2 * s1;
  float kb = k2 * c2 + k1 * s2;

  qh[base + d]      = __float2half_rn(qa);
  qh[base + d + 64] = __float2half_rn(qb);
  kh[base + d]      = __float2half_rn(ka);
  kh[base + d + 64] = __float2half_rn(kb);
}

// ---------------------------------------------------------------------------
// Flash attention, all-fp16 MMA, exp2 softmax. KV tiles widened to 64 rows:
// per kv-element the barrier count, softmax fixed sequence (max shuffles,
// alpha exp2, Oa rescale) and loop overhead all halve. 2 stages, 2 CTAs/SM.
// ---------------------------------------------------------------------------
#define KSTR 136
#define Q_ROWS 64
#define KV_ROWS 64
#define KH_BYTES (KV_ROWS * KSTR * 2)          // 17408
#define STAGE_BYTES (2 * KH_BYTES)             // K + V = 34816
#define A_SMEM (2 * STAGE_BYTES)               // 69632

__global__ __launch_bounds__(128, 2) void attn_h(
    const __half* __restrict__ qh, const __half* __restrict__ kh,
    const __half* __restrict__ vh, __half* __restrict__ O)
{
  extern __shared__ char sma[];
  const uint32_t sb = smem_u32(sma);
  const int tid  = threadIdx.x;
  const int wid  = tid >> 5;
  const int lane = tid & 31;
  const int q0 = blockIdx.x << 6;
  const int b  = blockIdx.y >> 4;
  const int h  = blockIdx.y & 15;
  const int warp_m = wid << 4;

  const size_t bS = (size_t)b * S_LEN;
  const size_t h128 = (size_t)h * HD;

  auto issue_kv = [&](int t) {
    const uint32_t stb = sb + (uint32_t)(t & 1) * STAGE_BYTES;
    const int kv0 = t << 6;
#pragma unroll
    for (int i = 0; i < 8; i++) {
      int u = tid + (i << 7);
      int row = u >> 4, c8 = (u & 15) << 3;
      size_t g = (bS + kv0 + row) * HID + h128 + c8;
      uint32_t so = (uint32_t)(row * KSTR + c8) * 2;
      CP_ASYNC16(stb + so,            kh + g);
      CP_ASYNC16(stb + KH_BYTES + so, vh + g);
    }
    CP_COMMIT();
  };
  issue_kv(0);
  issue_kv(1);

  // ---- Q fp16 fragments via direct LDG (m16n8k16 A-frag layout)
  uint32_t aQ[8][4];
  {
    const int r0 = warp_m + (lane >> 2);
    const int c0 = (lane & 3) << 1;
    const __half* gq = qh + (bS + q0 + r0) * HID + h128 + c0;
#pragma unroll
    for (int ks = 0; ks < 8; ks++) {
      const __half* p = gq + (ks << 4);
      aQ[ks][0] = *(const uint32_t*)(p);
      aQ[ks][1] = *(const uint32_t*)(p + 8 * HID);
      aQ[ks][2] = *(const uint32_t*)(p + 8);
      aQ[ks][3] = *(const uint32_t*)(p + 8 * HID + 8);
    }
  }

  float m0 = -1e30f, m1 = -1e30f, l0 = 0.f, l1 = 0.f;
  float Oa[16][4];
#pragma unroll
  for (int j = 0; j < 16; j++)
#pragma unroll
    for (int r = 0; r < 4; r++) Oa[j][r] = 0.f;

  const int NT = S_LEN / KV_ROWS;   // 32
  for (int t = 0; t < NT; t++) {
    if (t < NT - 1) CP_WAIT1(); else CP_WAIT0();
    __syncthreads();

    const uint32_t stb = sb + (uint32_t)(t & 1) * STAGE_BYTES;
    const uint32_t sK = stb;
    const uint32_t sV = stb + KH_BYTES;

    // ---- QK(t): 16 x 64 scores
    float S[8][4];
#pragma unroll
    for (int j = 0; j < 8; j++)
#pragma unroll
      for (int r = 0; r < 4; r++) S[j][r] = 0.f;

#pragma unroll
    for (int kc = 0; kc < 8; kc++) {
#pragma unroll
      for (int np = 0; np < 4; np++) {
        uint32_t bK[4];
        const uint32_t koff =
            (uint32_t)(((np << 4) + (lane & 7) + (((lane >> 4) & 1) << 3)) * KSTR
                       + (kc << 4) + (((lane >> 3) & 1) << 3)) * 2;
        ldsm4(sK + koff, bK[0], bK[1], bK[2], bK[3]);
        mma16816h(S[np * 2],     aQ[kc], bK);
        mma16816h(S[np * 2 + 1], aQ[kc], bK + 2);
      }
    }

    // ---- softmax(t) (exp2 domain)
    float mx0 = m0, mx1 = m1;
#pragma unroll
    for (int j = 0; j < 8; j++) {
      mx0 = fmaxf(mx0, fmaxf(S[j][0], S[j][1]));
      mx1 = fmaxf(mx1, fmaxf(S[j][2], S[j][3]));
    }
    mx0 = fmaxf(mx0, __shfl_xor_sync(0xffffffffu, mx0, 1));
    mx0 = fmaxf(mx0, __shfl_xor_sync(0xffffffffu, mx0, 2));
    mx1 = fmaxf(mx1, __shfl_xor_sync(0xffffffffu, mx1, 1));
    mx1 = fmaxf(mx1, __shfl_xor_sync(0xffffffffu, mx1, 2));
    const float al0 = exp2p(m0 - mx0);
    const float al1 = exp2p(m1 - mx1);
    m0 = mx0; m1 = mx1;

    uint32_t ph[8][2];
    float sum0 = 0.f, sum1 = 0.f;
#pragma unroll
    for (int j = 0; j < 8; j++) {
      float p00 = exp2p(S[j][0] - mx0);
      float p01 = exp2p(S[j][1] - mx0);
      float p10 = exp2p(S[j][2] - mx1);
      float p11 = exp2p(S[j][3] - mx1);
      sum0 += p00 + p01;
      sum1 += p10 + p11;
      ph[j][0] = pack_h(p00, p01);
      ph[j][1] = pack_h(p10, p11);
    }
    l0 = l0 * al0 + sum0;
    l1 = l1 * al1 + sum1;
#pragma unroll
    for (int j = 0; j < 16; j++) {
      Oa[j][0] *= al0; Oa[j][1] *= al0;
      Oa[j][2] *= al1; Oa[j][3] *= al1;
    }

    // ---- PV(t): fp16 single pass over 64 kv rows
#pragma unroll
    for (int kk = 0; kk < 4; kk++) {
      uint32_t paH[4] = {ph[kk*2][0], ph[kk*2][1], ph[kk*2+1][0], ph[kk*2+1][1]};
#pragma unroll
      for (int dp = 0; dp < 8; dp++) {
        uint32_t bV[4];
        const uint32_t voff =
            (uint32_t)(((kk << 4) + (lane & 7) + (((lane >> 3) & 1) << 3)) * KSTR
                       + (dp << 4) + ((lane >> 4) << 3)) * 2;
        ldsm4t(sV + voff, bV[0], bV[1], bV[2], bV[3]);
        mma16816h(Oa[dp * 2],     paH, bV);
        mma16816h(Oa[dp * 2 + 1], paH, bV + 2);
      }
    }

    __syncthreads();
    if (t + 2 < NT) issue_kv(t + 2);
  }

  // ---- epilogue (fp16 out)
  l0 += __shfl_xor_sync(0xffffffffu, l0, 1);
  l0 += __shfl_xor_sync(0xffffffffu, l0, 2);
  l1 += __shfl_xor_sync(0xffffffffu, l1, 1);
  l1 += __shfl_xor_sync(0xffffffffu, l1, 2);
  const float inv0 = 1.f / l0;
  const float inv1 = 1.f / l1;
  const int row0 = q0 + warp_m + (lane >> 2);
  const int cofs = (lane & 3) << 1;
#pragma unroll
  for (int j = 0; j < 16; j++) {
    const int col = (j << 3) + cofs;
    *(uint32_t*)&O[(bS + row0) * HID + h128 + col] =
        pack_h(Oa[j][0] * inv0, Oa[j][1] * inv0);
    *(uint32_t*)&O[(bS + row0 + 8) * HID + h128 + col] =
        pack_h(Oa[j][2] * inv1, Oa[j][3] * inv1);
  }
}

// ---------------------------------------------------------------------------
extern "C" void kernel_launch(void* const* d_in, const int* in_sizes, int n_in,
                              void* d_out, int out_size)
{
  (void)in_sizes; (void)n_in; (void)out_size;
  const float* x    = (const float*)d_in[0];
  const float* cosb = (const float*)d_in[1];
  const float* sinb = (const float*)d_in[2];
  const float* wq   = (const float*)d_in[3];
  const float* bq   = (const float*)d_in[4];
  const float* wk   = (const float*)d_in[5];
  const float* bk   = (const float*)d_in[6];
  const float* wv   = (const float*)d_in[7];
  const float* bv   = (const float*)d_in[8];
  const float* wo   = (const float*)d_in[9];
  float* out = (float*)d_out;

  float *q, *k;
  cudaGetSymbolAddress((void**)&q,  g_q);
  cudaGetSymbolAddress((void**)&k,  g_k);

  __half *xh, *wh, *qh, *kh, *vh, *aoh;
  cudaGetSymbolAddress((void**)&xh,  g_xh);
  cudaGetSymbolAddress((void**)&wh,  g_wh);
  cudaGetSymbolAddress((void**)&qh,  g_qh);
  cudaGetSymbolAddress((void**)&kh,  g_kh);
  cudaGetSymbolAddress((void**)&vh,  g_vh);
  cudaGetSymbolAddress((void**)&aoh, g_aoh);

  static bool attrs_set = false;
  if (!attrs_set) {
    cudaFuncSetAttribute(gemm_h,
                         cudaFuncAttributeMaxDynamicSharedMemorySize, GEMM_H_SMEM);
    cudaFuncSetAttribute(attn_h,
                         cudaFuncAttributeMaxDynamicSharedMemorySize, A_SMEM);
    attrs_set = true;
  }

  const int NX = MROWS * HID;
  const int NW = HID * HID;
  const size_t WS = (size_t)HID * HID;

  cvt_h<<<NX / 2048, 256>>>(x,  xh, NX);
  cvt_h<<<NW / 2048, 256>>>(wq, wh + 0 * WS, NW);
  cvt_h<<<NW / 2048, 256>>>(wk, wh + 1 * WS, NW);
  cvt_h<<<NW / 2048, 256>>>(wv, wh + 2 * WS, NW);
  cvt_h<<<NW / 2048, 256>>>(wo, wh + 3 * WS, NW);

  dim3 gg(HID / 128, MROWS / 128);  // (16, 32)
  gemm_h<<<gg, 256, GEMM_H_SMEM>>>(xh, wh + 0 * WS, bq, q, nullptr);
  gemm_h<<<gg, 256, GEMM_H_SMEM>>>(xh, wh + 1 * WS, bk, k, nullptr);
  gemm_h<<<gg, 256, GEMM_H_SMEM>>>(xh, wh + 2 * WS, bv, nullptr, vh);

  rope_h<<<(MROWS * NH * 64) / 256, 256>>>(q, k, cosb, sinb, qh, kh);

  attn_h<<<dim3(S_LEN / Q_ROWS, BATCH * NH), 128, A_SMEM>>>(qh, kh, vh, aoh);

  gemm_h<<<gg, 256, GEMM_H_SMEM>>>(aoh, wh + 3 * WS, nullptr, out, nullptr);
}